// round 1
// baseline (speedup 1.0000x reference)
#include <cuda_runtime.h>
#include <math.h>

#define H   256
#define NHh 4
#define HDd 64
#define Bb  2
#define Qq  8
#define Tt  512
#define EBb 16
#define BT  1024
#define NEGc (-0.6065306597126334f)
#define EPSc 0.00064f

// ---------------- scratch (device globals; no allocations) ----------------
__device__ float g_Xk [BT*H];
__device__ float g_Xv [BT*H];
__device__ float g_Xwh[BT*H];
__device__ float g_Xah[BT*H];
__device__ float g_K  [BT*H];
__device__ float g_KK [BT*H];
__device__ float g_Vb [BT*H];
__device__ float g_sigv[BT*H];
__device__ float g_hA [BT*H];
__device__ float g_Hw1[BT*32];
__device__ float g_t32[BT*32];
__device__ float g_Xr16[EBb*H];
__device__ float g_Xg16[EBb*H];
__device__ float g_Xw16[EBb*H];
__device__ float g_Xa16[EBb*H];
__device__ float g_qw1[EBb*32];
__device__ float g_qA [EBb*H];
__device__ float g_tq [EBb*64];
__device__ float g_rlast[EBb*H];
__device__ float g_glast[EBb*H];
__device__ float g_o  [EBb*H];
__device__ float g_ew [EBb*Tt*H];
__device__ float g_kf [EBb*Tt*H];
__device__ float g_bv [EBb*Tt*H];
__device__ float g_vv [EBb*Tt*H];

__device__ __forceinline__ float sigmoidf_(float x) { return 1.f / (1.f + expf(-x)); }

// ---------------- K1: per-(b,t) token-shift mixes ----------------
__global__ void k_prep_bt(const float* __restrict__ keyval,
                          const float* __restrict__ xk_, const float* __restrict__ xv_,
                          const float* __restrict__ xw_, const float* __restrict__ xa_) {
    int bt = blockIdx.x; int j = threadIdx.x;
    int b = bt / Tt, t = bt % Tt;
    float hs = keyval[(b*Tt + t)*H + j];
    float hp = (t > 0) ? keyval[(b*Tt + t - 1)*H + j] : 0.f;
    float dk = hp - hs;
    g_Xk [bt*H + j] = hs + dk * xk_[j];
    g_Xv [bt*H + j] = hs + dk * xv_[j];
    g_Xwh[bt*H + j] = hs * (1.f - xw_[j]);
    g_Xah[bt*H + j] = hs * (1.f - xa_[j]);
}

// ---------------- K2: per-eb (last-step / query-side) mixes ----------------
__global__ void k_prep_q(const float* __restrict__ query, const float* __restrict__ keyval,
                         const float* __restrict__ xr_, const float* __restrict__ xg_,
                         const float* __restrict__ xw_, const float* __restrict__ xa_) {
    int eb = blockIdx.x; int j = threadIdx.x;
    int b = eb / Qq, q = eb % Qq;
    float qv = query[(b*Qq + q)*H + j];
    float hsL = keyval[(b*Tt + Tt - 1)*H + j];
    g_Xr16[eb*H + j] = hsL * (1.f - xr_[j]) + qv * xr_[j];
    g_Xg16[eb*H + j] = hsL * (1.f - xg_[j]) + qv * xg_[j];
    g_Xw16[eb*H + j] = qv * xw_[j];
    g_Xa16[eb*H + j] = qv * xa_[j];
}

// ---------------- generic NT GEMM: C[m,n] = sum_k A[m,K+k] * W[n*K+k] ----------------
__global__ void gemm_nt(const float* __restrict__ A, const float* __restrict__ W,
                        float* __restrict__ C, int M, int N, int K) {
    __shared__ float As[64][17];
    __shared__ float Ws[64][17];
    int tid = threadIdx.x;
    int tx = tid % 16, ty = tid / 16;
    int bm = blockIdx.x * 64, bn = blockIdx.y * 64;
    float acc[4][4] = {};
    for (int k0 = 0; k0 < K; k0 += 16) {
        for (int l = tid; l < 64*16; l += 256) {
            int r = l >> 4, c = l & 15;
            As[r][c] = (bm + r < M) ? A[(bm + r)*K + k0 + c] : 0.f;
            Ws[r][c] = (bn + r < N) ? W[(bn + r)*K + k0 + c] : 0.f;
        }
        __syncthreads();
        #pragma unroll
        for (int kk = 0; kk < 16; kk++) {
            float a_[4], w_[4];
            #pragma unroll
            for (int i = 0; i < 4; i++) { a_[i] = As[ty + 16*i][kk]; w_[i] = Ws[tx + 16*i][kk]; }
            #pragma unroll
            for (int i = 0; i < 4; i++)
                #pragma unroll
                for (int jj = 0; jj < 4; jj++) acc[i][jj] += a_[i] * w_[jj];
        }
        __syncthreads();
    }
    for (int i = 0; i < 4; i++)
        for (int jj = 0; jj < 4; jj++) {
            int m = bm + ty + 16*i, n = bn + tx + 16*jj;
            if (m < M && n < N) C[m*N + n] = acc[i][jj];
        }
}

// ---------------- small-N NN GEMM: C[M,N] = A[M,K] @ w[K,N] (w row-major) ----------------
__global__ void k_mm_small(const float* __restrict__ A, const float* __restrict__ w,
                           float* __restrict__ C, int K, int N, int epi_sigmoid) {
    int m = blockIdx.x; int ln = threadIdx.x;   // blockDim = 32
    for (int n = ln; n < N; n += 32) {
        float acc = 0.f;
        for (int k = 0; k < K; k++) acc += A[m*K + k] * w[k*N + n];
        if (epi_sigmoid) acc = sigmoidf_(acc);
        C[m*N + n] = acc;
    }
}

// ---------------- wide GEMM: C[M,H] = T[M,Kd] @ w2[Kd,H], optional sigmoid(bias+x) ----------------
__global__ void k_mm_wide(const float* __restrict__ Tm, const float* __restrict__ w2,
                          const float* __restrict__ bias, float* __restrict__ C,
                          int Kd, int epi_sigmoid) {
    int m = blockIdx.x; int j = threadIdx.x;   // blockDim = 256
    __shared__ float sh[64];
    if (j < Kd) sh[j] = Tm[m*Kd + j];
    __syncthreads();
    float acc = 0.f;
    for (int d = 0; d < Kd; d++) acc += sh[d] * w2[d*H + j];
    if (epi_sigmoid) acc = sigmoidf_(acc + bias[j]);
    C[m*H + j] = acc;
}

// ---------------- kk = headwise-L2-normalize(k * k_k) ----------------
__global__ void k_kk(const float* __restrict__ kkp) {
    int bt = blockIdx.x, j = threadIdx.x;
    float kk = g_K[bt*H + j] * kkp[j];
    float sq = kk * kk;
    #pragma unroll
    for (int o = 16; o; o >>= 1) sq += __shfl_xor_sync(0xffffffffu, sq, o);
    __shared__ float ws[8];
    if ((j & 31) == 0) ws[j >> 5] = sq;
    __syncthreads();
    int head = j / HDd;
    float nrm = sqrtf(ws[2*head] + ws[2*head + 1]);
    g_KK[bt*H + j] = kk / fmaxf(nrm, 1e-12f);
}

// ---------------- per-(eb,t): w decay, a4, k_final, b-vec, v ----------------
__global__ void k_stage3(const float* __restrict__ v_first, const float* __restrict__ w2,
                         const float* __restrict__ w0, const float* __restrict__ a0,
                         const float* __restrict__ kap) {
    int t = blockIdx.x, eb = blockIdx.y;
    int b = eb / Qq;
    int bt = b*Tt + t;
    int j = threadIdx.x;
    __shared__ float th[32];
    if (j < 32) th[j] = tanhf(g_Hw1[bt*32 + j] + g_qw1[eb*32 + j]);
    __syncthreads();
    float acc = 0.f;
    #pragma unroll
    for (int d = 0; d < 32; d++) acc += th[d] * w2[d*H + j];
    float wv = NEGc * sigmoidf_(w0[j] + acc);
    float ew = expf(wv);
    float a4 = sigmoidf_(a0[j] + g_hA[bt*H + j] + g_qA[eb*H + j]);
    float kv = g_K[bt*H + j];
    float kf = kv * (1.f + (a4 - 1.f) * kap[j]);
    float bv = g_KK[bt*H + j] * a4;
    float vb = g_Vb[bt*H + j];
    float sv = g_sigv[bt*H + j];
    float vf = v_first[(eb*Tt + t)*H + j];
    float vv = vb + (vf - vb) * sv;
    int idx = (eb*Tt + t)*H + j;
    g_ew[idx] = ew; g_kf[idx] = kf; g_bv[idx] = bv; g_vv[idx] = vv;
}

// ---------------- backward vector scan + groupnorm + residual + gate ----------------
__global__ void k_scan(const float* __restrict__ r_k,
                       const float* __restrict__ gn_w, const float* __restrict__ gn_b) {
    int eb = blockIdx.x;
    int h = threadIdx.x >> 5, ln = threadIdx.x & 31;
    int b = eb / Qq;
    int i0 = h*HDd + ln, i1 = i0 + 32;
    float u0 = g_rlast[eb*H + i0], u1 = g_rlast[eb*H + i1];
    float o0 = 0.f, o1 = 0.f;
    for (int t = Tt - 1; t >= 0; --t) {
        int base = (eb*Tt + t)*H;
        int btb  = (b*Tt + t)*H;
        float k0 = g_kf[base + i0], k1 = g_kf[base + i1];
        float v0 = g_vv[base + i0], v1 = g_vv[base + i1];
        float bb0 = g_bv[base + i0], bb1 = g_bv[base + i1];
        float d0 = g_ew[base + i0], d1 = g_ew[base + i1];
        float n0 = g_KK[btb + i0], n1 = g_KK[btb + i1];  // a = -kk
        float c = u0*k0 + u1*k1;
        float s = u0*bb0 + u1*bb1;
        #pragma unroll
        for (int off = 16; off; off >>= 1) {
            c += __shfl_xor_sync(0xffffffffu, c, off);
            s += __shfl_xor_sync(0xffffffffu, s, off);
        }
        o0 += c * v0; o1 += c * v1;
        u0 = u0*d0 - s*n0;
        u1 = u1*d1 - s*n1;
    }
    // groupnorm over the head's 64 values
    float ms = o0 + o1, sq = o0*o0 + o1*o1;
    #pragma unroll
    for (int off = 16; off; off >>= 1) {
        ms += __shfl_xor_sync(0xffffffffu, ms, off);
        sq += __shfl_xor_sync(0xffffffffu, sq, off);
    }
    float mean = ms * (1.f/64.f);
    float var  = sq * (1.f/64.f) - mean*mean;
    float inv  = rsqrtf(var + EPSc);
    float on0 = (o0 - mean)*inv*gn_w[i0] + gn_b[i0];
    float on1 = (o1 - mean)*inv*gn_w[i1] + gn_b[i1];
    // residual: ((r*k_final*r_k).sum_k) * v  at t = T-1
    int lastb = (eb*Tt + (Tt - 1))*H;
    float r0 = g_rlast[eb*H + i0], r1 = g_rlast[eb*H + i1];
    float rr = r0 * g_kf[lastb + i0] * r_k[i0] + r1 * g_kf[lastb + i1] * r_k[i1];
    #pragma unroll
    for (int off = 16; off; off >>= 1) rr += __shfl_xor_sync(0xffffffffu, rr, off);
    on0 += rr * g_vv[lastb + i0];
    on1 += rr * g_vv[lastb + i1];
    on0 *= g_glast[eb*H + i0];
    on1 *= g_glast[eb*H + i1];
    g_o[eb*H + i0] = on0;
    g_o[eb*H + i1] = on1;
}

// ---------------- launch ----------------
extern "C" void kernel_launch(void* const* d_in, const int* in_sizes, int n_in,
                              void* d_out, int out_size) {
    const float* query   = (const float*)d_in[0];
    const float* keyval  = (const float*)d_in[1];
    const float* v_first = (const float*)d_in[2];
    const float* x_r = (const float*)d_in[3];
    const float* x_w = (const float*)d_in[4];
    const float* x_k = (const float*)d_in[5];
    const float* x_v = (const float*)d_in[6];
    const float* x_a = (const float*)d_in[7];
    const float* x_g = (const float*)d_in[8];
    const float* w0  = (const float*)d_in[9];
    const float* w1  = (const float*)d_in[10];
    const float* w2  = (const float*)d_in[11];
    const float* a0  = (const float*)d_in[12];
    const float* a1  = (const float*)d_in[13];
    const float* a2  = (const float*)d_in[14];
    const float* v0  = (const float*)d_in[15];
    const float* v1  = (const float*)d_in[16];
    const float* v2  = (const float*)d_in[17];
    const float* g1  = (const float*)d_in[18];
    const float* g2  = (const float*)d_in[19];
    const float* k_k = (const float*)d_in[20];
    const float* k_a = (const float*)d_in[21];
    const float* r_k = (const float*)d_in[22];
    const float* Wr  = (const float*)d_in[23];
    const float* Wk  = (const float*)d_in[24];
    const float* Wv  = (const float*)d_in[25];
    const float* Wo  = (const float*)d_in[26];
    const float* gn_w = (const float*)d_in[27];
    const float* gn_b = (const float*)d_in[28];
    float* out = (float*)d_out;

    float *pXk, *pXv, *pXwh, *pXah, *pK, *pKK, *pVb, *psv, *phA, *pHw1, *pt32;
    float *pXr, *pXg, *pXw, *pXa, *pqw1, *pqA, *ptq, *prl, *pgl, *po;
    cudaGetSymbolAddress((void**)&pXk,  g_Xk);
    cudaGetSymbolAddress((void**)&pXv,  g_Xv);
    cudaGetSymbolAddress((void**)&pXwh, g_Xwh);
    cudaGetSymbolAddress((void**)&pXah, g_Xah);
    cudaGetSymbolAddress((void**)&pK,   g_K);
    cudaGetSymbolAddress((void**)&pKK,  g_KK);
    cudaGetSymbolAddress((void**)&pVb,  g_Vb);
    cudaGetSymbolAddress((void**)&psv,  g_sigv);
    cudaGetSymbolAddress((void**)&phA,  g_hA);
    cudaGetSymbolAddress((void**)&pHw1, g_Hw1);
    cudaGetSymbolAddress((void**)&pt32, g_t32);
    cudaGetSymbolAddress((void**)&pXr,  g_Xr16);
    cudaGetSymbolAddress((void**)&pXg,  g_Xg16);
    cudaGetSymbolAddress((void**)&pXw,  g_Xw16);
    cudaGetSymbolAddress((void**)&pXa,  g_Xa16);
    cudaGetSymbolAddress((void**)&pqw1, g_qw1);
    cudaGetSymbolAddress((void**)&pqA,  g_qA);
    cudaGetSymbolAddress((void**)&ptq,  g_tq);
    cudaGetSymbolAddress((void**)&prl,  g_rlast);
    cudaGetSymbolAddress((void**)&pgl,  g_glast);
    cudaGetSymbolAddress((void**)&po,   g_o);

    k_prep_bt<<<BT, H>>>(keyval, x_k, x_v, x_w, x_a);
    k_prep_q<<<EBb, H>>>(query, keyval, x_r, x_g, x_w, x_a);

    gemm_nt<<<dim3(BT/64, H/64), 256>>>(pXk, Wk, pK, BT, H, H);
    gemm_nt<<<dim3(BT/64, H/64), 256>>>(pXv, Wv, pVb, BT, H, H);
    gemm_nt<<<dim3(1, H/64), 256>>>(pXr, Wr, prl, EBb, H, H);

    // w path
    k_mm_small<<<BT, 32>>>(pXwh, w1, pHw1, H, 32, 0);
    k_mm_small<<<EBb, 32>>>(pXw, w1, pqw1, H, 32, 0);
    // sig_v path
    k_mm_small<<<BT, 32>>>(pXv, v1, pt32, H, 32, 0);
    k_mm_wide<<<BT, H>>>(pt32, v2, v0, psv, 32, 1);
    // a path (per-(b,t) part)
    k_mm_small<<<BT, 32>>>(pXah, a1, pt32, H, 32, 0);
    k_mm_wide<<<BT, H>>>(pt32, a2, nullptr, phA, 32, 0);
    // a path (per-eb part)
    k_mm_small<<<EBb, 32>>>(pXa, a1, ptq, H, 32, 0);
    k_mm_wide<<<EBb, H>>>(ptq, a2, nullptr, pqA, 32, 0);
    // g path (per-eb, last step only)
    k_mm_small<<<EBb, 32>>>(pXg, g1, ptq, H, 64, 1);
    k_mm_wide<<<EBb, H>>>(ptq, g2, nullptr, pgl, 64, 0);

    k_kk<<<BT, H>>>(k_k);
    k_stage3<<<dim3(Tt, EBb), H>>>(v_first, w2, w0, a0, k_a);
    k_scan<<<EBb, 128>>>(r_k, gn_w, gn_b);

    gemm_nt<<<dim3(1, H/64), 256>>>(po, Wo, out, EBb, H, H);
    (void)in_sizes; (void)n_in; (void)out_size;
}

// round 3
// speedup vs baseline: 2.1822x; 2.1822x over previous
#include <cuda_runtime.h>
#include <math.h>

#define H   256
#define HD  64
#define Bb  2
#define Qq  8
#define Tt  512
#define NP  256          // number of timestep pairs
#define EB  16
#define BT  1024
#define NEGc (-0.6065306597126334f)
#define EPSc 0.00064f

// ---------------- scratch (device globals; no allocations) ----------------
__device__ float g_K  [BT*H];
__device__ float g_Vb [BT*H];
__device__ float g_KK [BT*H];
__device__ float g_sigv[BT*H];
__device__ float g_hA [BT*H];
__device__ float g_Hw1[BT*32];
__device__ float g_qw1[EB*32];
__device__ float g_qA [EB*H];
__device__ float g_rlast[EB*H];
__device__ float g_glast[EB*H];
__device__ float g_o  [EB*H];
__device__ float4 g_Pa [(size_t)EB*NP*H];   // {kf1, bv1, F1, F2}
__device__ float4 g_Pb [(size_t)EB*NP*H];   // {E, G, kk0, vv1}
__device__ float  g_Pv0[(size_t)EB*NP*H];   // vv0
__device__ float2 g_q  [EB*NP*4];           // per-head {q1, q2}

__device__ __forceinline__ float sigmoidf_(float x) { return 1.f / (1.f + __expf(-x)); }

__device__ __forceinline__ float wsum(float v) {
    #pragma unroll
    for (int o = 16; o; o >>= 1) v += __shfl_xor_sync(0xffffffffu, v, o);
    return v;
}

// ---------------- kA: K = Xk@Wk^T, Vb = Xv@Wv^T (Xk/Xv built on the fly) ----------------
__global__ void k_gemm_kv(const float* __restrict__ keyval,
                          const float* __restrict__ x_k, const float* __restrict__ x_v,
                          const float* __restrict__ Wk, const float* __restrict__ Wv) {
    const int z = blockIdx.z;
    const float* __restrict__ xm = z ? x_v : x_k;
    const float* __restrict__ W  = z ? Wv  : Wk;
    float* __restrict__ C = z ? g_Vb : g_K;
    __shared__ float As[64][33];
    __shared__ float Ws[64][33];
    int tid = threadIdx.x;
    int tx = tid & 15, ty = tid >> 4;
    int bm = blockIdx.x * 64, bn = blockIdx.y * 64;
    float acc[4][4] = {};
    #pragma unroll 1
    for (int k0 = 0; k0 < H; k0 += 32) {
        #pragma unroll
        for (int l = tid; l < 64*32; l += 256) {
            int r = l >> 5, c = l & 31;
            int m = bm + r, kg = k0 + c;
            int t = m & (Tt - 1);
            float hs = keyval[m*H + kg];
            float hp = (t > 0) ? keyval[(m-1)*H + kg] : 0.f;
            As[r][c] = fmaf(hp - hs, __ldg(&xm[kg]), hs);
            Ws[r][c] = W[(bn + r)*H + kg];
        }
        __syncthreads();
        #pragma unroll
        for (int kk = 0; kk < 32; kk++) {
            float a_[4], w_[4];
            #pragma unroll
            for (int i = 0; i < 4; i++) { a_[i] = As[ty + 16*i][kk]; w_[i] = Ws[tx + 16*i][kk]; }
            #pragma unroll
            for (int i = 0; i < 4; i++)
                #pragma unroll
                for (int jj = 0; jj < 4; jj++) acc[i][jj] = fmaf(a_[i], w_[jj], acc[i][jj]);
        }
        __syncthreads();
    }
    #pragma unroll
    for (int i = 0; i < 4; i++)
        #pragma unroll
        for (int jj = 0; jj < 4; jj++)
            C[(bm + ty + 16*i)*H + (bn + tx + 16*jj)] = acc[i][jj];
}

// ---------------- kB: fused per-bt small chains + kk-normalize ----------------
__global__ void k_bt(const float* __restrict__ keyval,
                     const float* __restrict__ x_v, const float* __restrict__ x_w,
                     const float* __restrict__ x_a,
                     const float* __restrict__ w1, const float* __restrict__ v1,
                     const float* __restrict__ a1,
                     const float* __restrict__ v2, const float* __restrict__ a2,
                     const float* __restrict__ v0, const float* __restrict__ k_k) {
    int bt = blockIdx.x; int j = threadIdx.x;
    int t = bt & (Tt - 1);
    __shared__ float xv_s[H], xw_s[H], xa_s[H];
    __shared__ float red[3][8][32];
    __shared__ float mid[3][32];
    __shared__ float ws2[8];
    float hs = keyval[bt*H + j];
    float hp = (t > 0) ? keyval[(bt-1)*H + j] : 0.f;
    xv_s[j] = fmaf(hp - hs, x_v[j], hs);
    xw_s[j] = hs * (1.f - x_w[j]);
    xa_s[j] = hs * (1.f - x_a[j]);
    __syncthreads();
    int w = j >> 5, ln = j & 31;
    int kbase = w * 32;
    float pw = 0.f, pv = 0.f, pa = 0.f;
    #pragma unroll
    for (int kk = 0; kk < 32; kk++) {
        int k = kbase + kk;
        pw = fmaf(xw_s[k], w1[k*32 + ln], pw);
        pv = fmaf(xv_s[k], v1[k*32 + ln], pv);
        pa = fmaf(xa_s[k], a1[k*32 + ln], pa);
    }
    red[0][w][ln] = pw; red[1][w][ln] = pv; red[2][w][ln] = pa;
    __syncthreads();
    if (j < 96) {
        int m = j >> 5, d = j & 31;
        float s = 0.f;
        #pragma unroll
        for (int ww = 0; ww < 8; ww++) s += red[m][ww][d];
        mid[m][d] = s;
        if (m == 0) g_Hw1[bt*32 + d] = s;
    }
    __syncthreads();
    float av = 0.f, aa = 0.f;
    #pragma unroll
    for (int d = 0; d < 32; d++) {
        av = fmaf(mid[1][d], v2[d*H + j], av);
        aa = fmaf(mid[2][d], a2[d*H + j], aa);
    }
    g_sigv[bt*H + j] = sigmoidf_(av + v0[j]);
    g_hA[bt*H + j]   = aa;
    float kkv = g_K[bt*H + j] * k_k[j];
    float sq = wsum(kkv * kkv);
    if (ln == 0) ws2[w] = sq;
    __syncthreads();
    int head = j >> 6;
    float nrm = sqrtf(ws2[2*head] + ws2[2*head + 1]);
    g_KK[bt*H + j] = kkv / fmaxf(nrm, 1e-12f);
}

// ---------------- kC: fused per-eb work (qw1, qA, glast, rlast=Xr@Wr^T) ----------------
__global__ void k_q(const float* __restrict__ query, const float* __restrict__ keyval,
                    const float* __restrict__ x_r, const float* __restrict__ x_g,
                    const float* __restrict__ x_w, const float* __restrict__ x_a,
                    const float* __restrict__ w1, const float* __restrict__ a1,
                    const float* __restrict__ g1, const float* __restrict__ a2,
                    const float* __restrict__ g2, const float* __restrict__ Wr) {
    int eb = blockIdx.x; int j = threadIdx.x;
    int b = eb >> 3;
    __shared__ float xr_s[H], xg_s[H], xw_s[H], xa_s[H];
    __shared__ float red[4][8][32];
    __shared__ float ta[32], tg[64];
    float qv  = query[eb*H + j];
    float hsL = keyval[(b*Tt + Tt - 1)*H + j];
    xr_s[j] = fmaf(qv - hsL, x_r[j], hsL);
    xg_s[j] = fmaf(qv - hsL, x_g[j], hsL);
    xw_s[j] = qv * x_w[j];
    xa_s[j] = qv * x_a[j];
    __syncthreads();
    int w = j >> 5, ln = j & 31;
    int kbase = w * 32;
    float pw = 0.f, pa = 0.f, pg0 = 0.f, pg1 = 0.f;
    #pragma unroll
    for (int kk = 0; kk < 32; kk++) {
        int k = kbase + kk;
        pw  = fmaf(xw_s[k], w1[k*32 + ln], pw);
        pa  = fmaf(xa_s[k], a1[k*32 + ln], pa);
        pg0 = fmaf(xg_s[k], g1[k*64 + ln], pg0);
        pg1 = fmaf(xg_s[k], g1[k*64 + 32 + ln], pg1);
    }
    red[0][w][ln] = pw; red[1][w][ln] = pa; red[2][w][ln] = pg0; red[3][w][ln] = pg1;
    __syncthreads();
    if (j < 128) {
        int m = j >> 5, d = j & 31;
        float s = 0.f;
        #pragma unroll
        for (int ww = 0; ww < 8; ww++) s += red[m][ww][d];
        if      (m == 0) g_qw1[eb*32 + d] = s;
        else if (m == 1) ta[d] = s;
        else if (m == 2) tg[d] = sigmoidf_(s);
        else             tg[32 + d] = sigmoidf_(s);
    }
    __syncthreads();
    float aa = 0.f, gg = 0.f;
    #pragma unroll
    for (int d = 0; d < 32; d++) aa = fmaf(ta[d], a2[d*H + j], aa);
    #pragma unroll
    for (int d = 0; d < 64; d++) gg = fmaf(tg[d], g2[d*H + j], gg);
    g_qA[eb*H + j]    = aa;
    g_glast[eb*H + j] = gg;
    float xrp[8];
    #pragma unroll
    for (int m = 0; m < 8; m++) xrp[m] = xr_s[ln*8 + m];
    #pragma unroll 1
    for (int rr = 0; rr < 32; rr++) {
        int n = rr*8 + w;
        const float4* Wrow = (const float4*)(Wr + n*H + ln*8);
        float4 a4 = Wrow[0], b4 = Wrow[1];
        float acc = xrp[0]*a4.x + xrp[1]*a4.y + xrp[2]*a4.z + xrp[3]*a4.w
                  + xrp[4]*b4.x + xrp[5]*b4.y + xrp[6]*b4.z + xrp[7]*b4.w;
        acc = wsum(acc);
        if (ln == 0) g_rlast[eb*H + n] = acc;
    }
}

// ---------------- kD: per-(eb, pair) scan-input precompute ----------------
// pair p covers t1 = 2p+1 (first in backward order) and t0 = 2p.
__global__ void k_pair(const float* __restrict__ v_first, const float* __restrict__ w2,
                       const float* __restrict__ w0, const float* __restrict__ a0,
                       const float* __restrict__ k_a) {
    int p = blockIdx.x, eb = blockIdx.y;
    int b = eb >> 3;
    int t1 = 2*p + 1, t0 = 2*p;
    int bt1 = b*Tt + t1, bt0 = b*Tt + t0;
    int j = threadIdx.x;
    __shared__ float th[2][32];
    __shared__ float sq[2][8];
    if (j < 64) {
        int m = j >> 5, d = j & 31;
        int btx = m ? bt0 : bt1;
        th[m][d] = tanhf(g_Hw1[btx*32 + d] + g_qw1[eb*32 + d]);
    }
    __syncthreads();
    float ac1 = 0.f, ac0 = 0.f;
    #pragma unroll
    for (int d = 0; d < 32; d++) {
        float wd = w2[d*H + j];
        ac1 = fmaf(th[0][d], wd, ac1);
        ac0 = fmaf(th[1][d], wd, ac0);
    }
    float w0j = w0[j], a0j = a0[j], kaj = k_a[j], qAj = g_qA[eb*H + j];
    float ew1 = __expf(NEGc * sigmoidf_(w0j + ac1));
    float ew0 = __expf(NEGc * sigmoidf_(w0j + ac0));
    float a41 = sigmoidf_(a0j + g_hA[bt1*H + j] + qAj);
    float a40 = sigmoidf_(a0j + g_hA[bt0*H + j] + qAj);
    float kf1 = g_K[bt1*H + j] * fmaf(a41 - 1.f, kaj, 1.f);
    float kf0 = g_K[bt0*H + j] * fmaf(a40 - 1.f, kaj, 1.f);
    float kk1 = g_KK[bt1*H + j];
    float kk0 = g_KK[bt0*H + j];
    float bv1 = kk1 * a41;
    float bv0 = kk0 * a40;
    float vb1 = g_Vb[bt1*H + j], sv1 = g_sigv[bt1*H + j];
    float vb0 = g_Vb[bt0*H + j], sv0 = g_sigv[bt0*H + j];
    float vv1 = fmaf(v_first[((size_t)eb*Tt + t1)*H + j] - vb1, sv1, vb1);
    float vv0 = fmaf(v_first[((size_t)eb*Tt + t0)*H + j] - vb0, sv0, vb0);
    size_t idx = ((size_t)eb*NP + p)*H + j;
    g_Pa[idx]  = make_float4(kf1, bv1, ew1*kf0, ew1*bv0);
    g_Pb[idx]  = make_float4(ew1*ew0, kk1*ew0, kk0, vv1);
    g_Pv0[idx] = vv0;
    // per-head scalars q1 = kk1·kf0, q2 = kk1·bv0 (dot over 64 head dims)
    float q1p = wsum(kk1 * kf0);
    float q2p = wsum(kk1 * bv0);
    int w = j >> 5, ln = j & 31;
    if (ln == 0) { sq[0][w] = q1p; sq[1][w] = q2p; }
    __syncthreads();
    if (j < 4) {
        float q1 = sq[0][2*j] + sq[0][2*j + 1];
        float q2 = sq[1][2*j] + sq[1][2*j + 1];
        g_q[(eb*NP + p)*4 + j] = make_float2(q1, q2);
    }
}

// ---------------- kE: backward scan (2 steps per reduction round) ----------------
__global__ void k_scan(const float* __restrict__ r_k,
                       const float* __restrict__ gn_w, const float* __restrict__ gn_b) {
    int eb = blockIdx.x;
    int h = threadIdx.x >> 5, ln = threadIdx.x & 31;
    int i0 = h*HD + ln, i1 = i0 + 32;
    float u0 = g_rlast[eb*H + i0], u1 = g_rlast[eb*H + i1];
    float o0 = 0.f, o1 = 0.f;
    const float4* __restrict__ Pa  = g_Pa  + (size_t)eb*NP*H;
    const float4* __restrict__ Pb  = g_Pb  + (size_t)eb*NP*H;
    const float*  __restrict__ Pv0 = g_Pv0 + (size_t)eb*NP*H;
    const float2* __restrict__ Qs  = g_q   + eb*NP*4;
    // prefetch p = NP-1
    size_t base = (size_t)(NP-1)*H;
    float4 a0v = Pa[base + i0], a1v = Pa[base + i1];
    float4 b0v = Pb[base + i0], b1v = Pb[base + i1];
    float  v00 = Pv0[base + i0], v01 = Pv0[base + i1];
    float2 qv  = Qs[(NP-1)*4 + h];
    for (int p = NP - 1; p >= 0; --p) {
        float4 A0 = a0v, A1 = a1v, B0 = b0v, B1 = b1v;
        float V0 = v00, V1 = v01;
        float2 Q = qv;
        if (p > 0) {
            size_t nb = (size_t)(p-1)*H;
            a0v = Pa[nb + i0]; a1v = Pa[nb + i1];
            b0v = Pb[nb + i0]; b1v = Pb[nb + i1];
            v00 = Pv0[nb + i0]; v01 = Pv0[nb + i1];
            qv  = Qs[(p-1)*4 + h];
        }
        // four independent reductions, interleaved butterflies
        float r1 = fmaf(u0, A0.x, u1*A1.x);   // c1 = u·kf1
        float r2 = fmaf(u0, A0.y, u1*A1.y);   // s1 = u·bv1
        float r3 = fmaf(u0, A0.z, u1*A1.z);   // m1 = u·(ew1∘kf0)
        float r4 = fmaf(u0, A0.w, u1*A1.w);   // m2 = u·(ew1∘bv0)
        #pragma unroll
        for (int off = 16; off; off >>= 1) {
            r1 += __shfl_xor_sync(0xffffffffu, r1, off);
            r2 += __shfl_xor_sync(0xffffffffu, r2, off);
            r3 += __shfl_xor_sync(0xffffffffu, r3, off);
            r4 += __shfl_xor_sync(0xffffffffu, r4, off);
        }
        float c0 = fmaf(-r2, Q.x, r3);
        float s0 = fmaf(-r2, Q.y, r4);
        o0 = fmaf(r1, B0.w, fmaf(c0, V0, o0));
        o1 = fmaf(r1, B1.w, fmaf(c0, V1, o1));
        u0 = fmaf(u0, B0.x, -fmaf(r2, B0.y, s0*B0.z));
        u1 = fmaf(u1, B1.x, -fmaf(r2, B1.y, s0*B1.z));
    }
    // groupnorm
    float ms = wsum(o0 + o1);
    float sqs = wsum(fmaf(o0, o0, o1*o1));
    float mean = ms * (1.f/64.f);
    float var  = sqs * (1.f/64.f) - mean*mean;
    float inv  = rsqrtf(var + EPSc);
    float on0 = fmaf((o0 - mean)*inv, gn_w[i0], gn_b[i0]);
    float on1 = fmaf((o1 - mean)*inv, gn_w[i1], gn_b[i1]);
    // residual at t = T-1 (pair NP-1: kf1 = Pa.x, vv1 = Pb.w)
    size_t lb = (size_t)(NP-1)*H;
    float4 La0 = Pa[lb + i0], La1 = Pa[lb + i1];
    float4 Lb0 = Pb[lb + i0], Lb1 = Pb[lb + i1];
    float r0 = g_rlast[eb*H + i0], r1l = g_rlast[eb*H + i1];
    float rr = wsum(r0*La0.x*r_k[i0] + r1l*La1.x*r_k[i1]);
    on0 = fmaf(rr, Lb0.w, on0);
    on1 = fmaf(rr, Lb1.w, on1);
    g_o[eb*H + i0] = on0 * g_glast[eb*H + i0];
    g_o[eb*H + i1] = on1 * g_glast[eb*H + i1];
}

// ---------------- kF: out = g_o @ Wo^T ----------------
__global__ void k_out(const float* __restrict__ Wo, float* __restrict__ out) {
    int eb = blockIdx.x; int j = threadIdx.x;
    int w = j >> 5, ln = j & 31;
    __shared__ float os[H];
    os[j] = g_o[eb*H + j];
    __syncthreads();
    float xp[8];
    #pragma unroll
    for (int m = 0; m < 8; m++) xp[m] = os[ln*8 + m];
    #pragma unroll 1
    for (int rr = 0; rr < 32; rr++) {
        int n = rr*8 + w;
        const float4* Wrow = (const float4*)(Wo + n*H + ln*8);
        float4 a4 = Wrow[0], b4 = Wrow[1];
        float acc = xp[0]*a4.x + xp[1]*a4.y + xp[2]*a4.z + xp[3]*a4.w
                  + xp[4]*b4.x + xp[5]*b4.y + xp[6]*b4.z + xp[7]*b4.w;
        acc = wsum(acc);
        if (ln == 0) out[eb*H + n] = acc;
    }
}

// ---------------- launch ----------------
extern "C" void kernel_launch(void* const* d_in, const int* in_sizes, int n_in,
                              void* d_out, int out_size) {
    const float* query   = (const float*)d_in[0];
    const float* keyval  = (const float*)d_in[1];
    const float* v_first = (const float*)d_in[2];
    const float* x_r = (const float*)d_in[3];
    const float* x_w = (const float*)d_in[4];
    const float* x_k = (const float*)d_in[5];
    const float* x_v = (const float*)d_in[6];
    const float* x_a = (const float*)d_in[7];
    const float* x_g = (const float*)d_in[8];
    const float* w0  = (const float*)d_in[9];
    const float* w1  = (const float*)d_in[10];
    const float* w2  = (const float*)d_in[11];
    const float* a0  = (const float*)d_in[12];
    const float* a1  = (const float*)d_in[13];
    const float* a2  = (const float*)d_in[14];
    const float* v0  = (const float*)d_in[15];
    const float* v1  = (const float*)d_in[16];
    const float* v2  = (const float*)d_in[17];
    const float* g1  = (const float*)d_in[18];
    const float* g2  = (const float*)d_in[19];
    const float* k_k = (const float*)d_in[20];
    const float* k_a = (const float*)d_in[21];
    const float* r_k = (const float*)d_in[22];
    const float* Wr  = (const float*)d_in[23];
    const float* Wk  = (const float*)d_in[24];
    const float* Wv  = (const float*)d_in[25];
    const float* Wo  = (const float*)d_in[26];
    const float* gn_w = (const float*)d_in[27];
    const float* gn_b = (const float*)d_in[28];
    float* out = (float*)d_out;

    k_gemm_kv<<<dim3(BT/64, H/64, 2), 256>>>(keyval, x_k, x_v, Wk, Wv);
    k_bt<<<BT, H>>>(keyval, x_v, x_w, x_a, w1, v1, a1, v2, a2, v0, k_k);
    k_q<<<EB, H>>>(query, keyval, x_r, x_g, x_w, x_a, w1, a1, g1, a2, g2, Wr);
    k_pair<<<dim3(NP, EB), H>>>(v_first, w2, w0, a0, k_a);
    k_scan<<<EB, 128>>>(r_k, gn_w, gn_b);
    k_out<<<EB, H>>>(Wo, out);
    (void)in_sizes; (void)n_in; (void)out_size;
}

// round 4
// speedup vs baseline: 3.2303x; 1.4803x over previous
#include <cuda_runtime.h>
#include <math.h>

#define H   256
#define HD  64
#define Bb  2
#define Qq  8
#define Tt  512
#define NP  256          // number of timestep pairs
#define EB  16
#define BT  1024
#define NEGc (-0.6065306597126334f)
#define EPSc 0.00064f

// ---------------- scratch (device globals; no allocations) ----------------
__device__ float g_K  [BT*H];
__device__ float g_Vb [BT*H];
__device__ float g_KK [BT*H];
__device__ float g_sigv[BT*H];
__device__ float g_hA [BT*H];
__device__ float g_Hw1[BT*32];
__device__ float g_qw1[EB*32];
__device__ float g_qA [EB*H];
__device__ float g_rlast[EB*H];
__device__ float g_glast[EB*H];
__device__ float g_o  [EB*H];
__device__ float4 g_Pa [(size_t)EB*NP*H];   // {kf1, bv1, F1=ew1*kf0, F2=ew1*bv0}
__device__ float4 g_Pb [(size_t)EB*NP*H];   // {E=ew1*ew0, G=kk1*ew0, kk0, vv1}
__device__ float  g_Pv0[(size_t)EB*NP*H];   // vv0
__device__ float2 g_q  [EB*NP*4];           // per-head {q1=kk1·kf0, q2=kk1·bv0}

__device__ __forceinline__ float sigmoidf_(float x) { return 1.f / (1.f + __expf(-x)); }

__device__ __forceinline__ float wsum(float v) {
    #pragma unroll
    for (int o = 16; o; o >>= 1) v += __shfl_xor_sync(0xffffffffu, v, o);
    return v;
}

// ---------------- kA: K = Xk@Wk^T, Vb = Xv@Wv^T (Xk/Xv built on the fly) ----------------
__global__ void k_gemm_kv(const float* __restrict__ keyval,
                          const float* __restrict__ x_k, const float* __restrict__ x_v,
                          const float* __restrict__ Wk, const float* __restrict__ Wv) {
    const int z = blockIdx.z;
    const float* __restrict__ xm = z ? x_v : x_k;
    const float* __restrict__ W  = z ? Wv  : Wk;
    float* __restrict__ C = z ? g_Vb : g_K;
    __shared__ float As[64][33];
    __shared__ float Ws[64][33];
    int tid = threadIdx.x;
    int tx = tid & 15, ty = tid >> 4;
    int bm = blockIdx.x * 64, bn = blockIdx.y * 64;
    float acc[4][4] = {};
    #pragma unroll 1
    for (int k0 = 0; k0 < H; k0 += 32) {
        #pragma unroll
        for (int l = tid; l < 64*32; l += 256) {
            int r = l >> 5, c = l & 31;
            int m = bm + r, kg = k0 + c;
            int t = m & (Tt - 1);
            float hs = keyval[m*H + kg];
            float hp = (t > 0) ? keyval[(m-1)*H + kg] : 0.f;
            As[r][c] = fmaf(hp - hs, __ldg(&xm[kg]), hs);
            Ws[r][c] = W[(bn + r)*H + kg];
        }
        __syncthreads();
        #pragma unroll
        for (int kk = 0; kk < 32; kk++) {
            float a_[4], w_[4];
            #pragma unroll
            for (int i = 0; i < 4; i++) { a_[i] = As[ty + 16*i][kk]; w_[i] = Ws[tx + 16*i][kk]; }
            #pragma unroll
            for (int i = 0; i < 4; i++)
                #pragma unroll
                for (int jj = 0; jj < 4; jj++) acc[i][jj] = fmaf(a_[i], w_[jj], acc[i][jj]);
        }
        __syncthreads();
    }
    #pragma unroll
    for (int i = 0; i < 4; i++)
        #pragma unroll
        for (int jj = 0; jj < 4; jj++)
            C[(bm + ty + 16*i)*H + (bn + tx + 16*jj)] = acc[i][jj];
}

// ---------------- kB: fused per-bt small chains + kk-normalize ----------------
__global__ void k_bt(const float* __restrict__ keyval,
                     const float* __restrict__ x_v, const float* __restrict__ x_w,
                     const float* __restrict__ x_a,
                     const float* __restrict__ w1, const float* __restrict__ v1,
                     const float* __restrict__ a1,
                     const float* __restrict__ v2, const float* __restrict__ a2,
                     const float* __restrict__ v0, const float* __restrict__ k_k) {
    int bt = blockIdx.x; int j = threadIdx.x;
    int t = bt & (Tt - 1);
    __shared__ float xv_s[H], xw_s[H], xa_s[H];
    __shared__ float red[3][8][32];
    __shared__ float mid[3][32];
    __shared__ float ws2[8];
    float hs = keyval[bt*H + j];
    float hp = (t > 0) ? keyval[(bt-1)*H + j] : 0.f;
    xv_s[j] = fmaf(hp - hs, x_v[j], hs);
    xw_s[j] = hs * (1.f - x_w[j]);
    xa_s[j] = hs * (1.f - x_a[j]);
    __syncthreads();
    int w = j >> 5, ln = j & 31;
    int kbase = w * 32;
    float pw = 0.f, pv = 0.f, pa = 0.f;
    #pragma unroll
    for (int kk = 0; kk < 32; kk++) {
        int k = kbase + kk;
        pw = fmaf(xw_s[k], w1[k*32 + ln], pw);
        pv = fmaf(xv_s[k], v1[k*32 + ln], pv);
        pa = fmaf(xa_s[k], a1[k*32 + ln], pa);
    }
    red[0][w][ln] = pw; red[1][w][ln] = pv; red[2][w][ln] = pa;
    __syncthreads();
    if (j < 96) {
        int m = j >> 5, d = j & 31;
        float s = 0.f;
        #pragma unroll
        for (int ww = 0; ww < 8; ww++) s += red[m][ww][d];
        mid[m][d] = s;
        if (m == 0) g_Hw1[bt*32 + d] = s;
    }
    __syncthreads();
    float av = 0.f, aa = 0.f;
    #pragma unroll
    for (int d = 0; d < 32; d++) {
        av = fmaf(mid[1][d], v2[d*H + j], av);
        aa = fmaf(mid[2][d], a2[d*H + j], aa);
    }
    g_sigv[bt*H + j] = sigmoidf_(av + v0[j]);
    g_hA[bt*H + j]   = aa;
    float kkv = g_K[bt*H + j] * k_k[j];
    float sq = wsum(kkv * kkv);
    if (ln == 0) ws2[w] = sq;
    __syncthreads();
    int head = j >> 6;
    float nrm = sqrtf(ws2[2*head] + ws2[2*head + 1]);
    g_KK[bt*H + j] = kkv / fmaxf(nrm, 1e-12f);
}

// ---------------- kC: fused per-eb work (qw1, qA, glast, rlast=Xr@Wr^T) ----------------
__global__ void k_q(const float* __restrict__ query, const float* __restrict__ keyval,
                    const float* __restrict__ x_r, const float* __restrict__ x_g,
                    const float* __restrict__ x_w, const float* __restrict__ x_a,
                    const float* __restrict__ w1, const float* __restrict__ a1,
                    const float* __restrict__ g1, const float* __restrict__ a2,
                    const float* __restrict__ g2, const float* __restrict__ Wr) {
    int eb = blockIdx.x; int j = threadIdx.x;
    int b = eb >> 3;
    __shared__ float xr_s[H], xg_s[H], xw_s[H], xa_s[H];
    __shared__ float red[4][8][32];
    __shared__ float ta[32], tg[64];
    float qv  = query[eb*H + j];
    float hsL = keyval[(b*Tt + Tt - 1)*H + j];
    xr_s[j] = fmaf(qv - hsL, x_r[j], hsL);
    xg_s[j] = fmaf(qv - hsL, x_g[j], hsL);
    xw_s[j] = qv * x_w[j];
    xa_s[j] = qv * x_a[j];
    __syncthreads();
    int w = j >> 5, ln = j & 31;
    int kbase = w * 32;
    float pw = 0.f, pa = 0.f, pg0 = 0.f, pg1 = 0.f;
    #pragma unroll
    for (int kk = 0; kk < 32; kk++) {
        int k = kbase + kk;
        pw  = fmaf(xw_s[k], w1[k*32 + ln], pw);
        pa  = fmaf(xa_s[k], a1[k*32 + ln], pa);
        pg0 = fmaf(xg_s[k], g1[k*64 + ln], pg0);
        pg1 = fmaf(xg_s[k], g1[k*64 + 32 + ln], pg1);
    }
    red[0][w][ln] = pw; red[1][w][ln] = pa; red[2][w][ln] = pg0; red[3][w][ln] = pg1;
    __syncthreads();
    if (j < 128) {
        int m = j >> 5, d = j & 31;
        float s = 0.f;
        #pragma unroll
        for (int ww = 0; ww < 8; ww++) s += red[m][ww][d];
        if      (m == 0) g_qw1[eb*32 + d] = s;
        else if (m == 1) ta[d] = s;
        else if (m == 2) tg[d] = sigmoidf_(s);
        else             tg[32 + d] = sigmoidf_(s);
    }
    __syncthreads();
    float aa = 0.f, gg = 0.f;
    #pragma unroll
    for (int d = 0; d < 32; d++) aa = fmaf(ta[d], a2[d*H + j], aa);
    #pragma unroll
    for (int d = 0; d < 64; d++) gg = fmaf(tg[d], g2[d*H + j], gg);
    g_qA[eb*H + j]    = aa;
    g_glast[eb*H + j] = gg;
    float xrp[8];
    #pragma unroll
    for (int m = 0; m < 8; m++) xrp[m] = xr_s[ln*8 + m];
    #pragma unroll 1
    for (int rr = 0; rr < 32; rr++) {
        int n = rr*8 + w;
        const float4* Wrow = (const float4*)(Wr + n*H + ln*8);
        float4 a4 = Wrow[0], b4 = Wrow[1];
        float acc = xrp[0]*a4.x + xrp[1]*a4.y + xrp[2]*a4.z + xrp[3]*a4.w
                  + xrp[4]*b4.x + xrp[5]*b4.y + xrp[6]*b4.z + xrp[7]*b4.w;
        acc = wsum(acc);
        if (ln == 0) g_rlast[eb*H + n] = acc;
    }
}

// ---------------- kD: per-(eb, pair) scan-input precompute ----------------
__global__ void k_pair(const float* __restrict__ v_first, const float* __restrict__ w2,
                       const float* __restrict__ w0, const float* __restrict__ a0,
                       const float* __restrict__ k_a) {
    int p = blockIdx.x, eb = blockIdx.y;
    int b = eb >> 3;
    int t1 = 2*p + 1, t0 = 2*p;
    int bt1 = b*Tt + t1, bt0 = b*Tt + t0;
    int j = threadIdx.x;
    __shared__ float th[2][32];
    __shared__ float sq[2][8];
    if (j < 64) {
        int m = j >> 5, d = j & 31;
        int btx = m ? bt0 : bt1;
        th[m][d] = tanhf(g_Hw1[btx*32 + d] + g_qw1[eb*32 + d]);
    }
    __syncthreads();
    float ac1 = 0.f, ac0 = 0.f;
    #pragma unroll
    for (int d = 0; d < 32; d++) {
        float wd = w2[d*H + j];
        ac1 = fmaf(th[0][d], wd, ac1);
        ac0 = fmaf(th[1][d], wd, ac0);
    }
    float w0j = w0[j], a0j = a0[j], kaj = k_a[j], qAj = g_qA[eb*H + j];
    float ew1 = __expf(NEGc * sigmoidf_(w0j + ac1));
    float ew0 = __expf(NEGc * sigmoidf_(w0j + ac0));
    float a41 = sigmoidf_(a0j + g_hA[bt1*H + j] + qAj);
    float a40 = sigmoidf_(a0j + g_hA[bt0*H + j] + qAj);
    float kf1 = g_K[bt1*H + j] * fmaf(a41 - 1.f, kaj, 1.f);
    float kf0 = g_K[bt0*H + j] * fmaf(a40 - 1.f, kaj, 1.f);
    float kk1 = g_KK[bt1*H + j];
    float kk0 = g_KK[bt0*H + j];
    float bv1 = kk1 * a41;
    float bv0 = kk0 * a40;
    float vb1 = g_Vb[bt1*H + j], sv1 = g_sigv[bt1*H + j];
    float vb0 = g_Vb[bt0*H + j], sv0 = g_sigv[bt0*H + j];
    float vv1 = fmaf(v_first[((size_t)eb*Tt + t1)*H + j] - vb1, sv1, vb1);
    float vv0 = fmaf(v_first[((size_t)eb*Tt + t0)*H + j] - vb0, sv0, vb0);
    size_t idx = ((size_t)eb*NP + p)*H + j;
    g_Pa[idx]  = make_float4(kf1, bv1, ew1*kf0, ew1*bv0);
    g_Pb[idx]  = make_float4(ew1*ew0, kk1*ew0, kk0, vv1);
    g_Pv0[idx] = vv0;
    float q1p = wsum(kk1 * kf0);
    float q2p = wsum(kk1 * bv0);
    int w = j >> 5, ln = j & 31;
    if (ln == 0) { sq[0][w] = q1p; sq[1][w] = q2p; }
    __syncthreads();
    if (j < 4) {
        float q1 = sq[0][2*j] + sq[0][2*j + 1];
        float q2 = sq[1][2*j] + sq[1][2*j + 1];
        g_q[(eb*NP + p)*4 + j] = make_float2(q1, q2);
    }
}

// ---------------- kE: backward scan, 1 warp per (eb, head), 4-deep prefetch ----------------
#define PF 4
__global__ void __launch_bounds__(32, 4) k_scan(const float* __restrict__ r_k,
                       const float* __restrict__ gn_w, const float* __restrict__ gn_b) {
    int wb = blockIdx.x;
    int eb = wb >> 2, h = wb & 3;
    int ln = threadIdx.x;
    int i0 = h*HD + ln, i1 = i0 + 32;
    float u0 = g_rlast[eb*H + i0], u1 = g_rlast[eb*H + i1];
    float o0 = 0.f, o1 = 0.f;
    const float4* __restrict__ Pa  = g_Pa  + (size_t)eb*NP*H;
    const float4* __restrict__ Pb  = g_Pb  + (size_t)eb*NP*H;
    const float*  __restrict__ Pv0 = g_Pv0 + (size_t)eb*NP*H;
    const float2* __restrict__ Qs  = g_q   + eb*NP*4;

    float4 A0[PF], A1[PF], B0[PF], B1[PF];
    float  V0[PF], V1[PF];
    float2 Qr[PF];
    #pragma unroll
    for (int s = 0; s < PF; s++) {
        int p = NP - 1 - s;
        size_t base = (size_t)p*H;
        A0[s] = Pa[base + i0]; A1[s] = Pa[base + i1];
        B0[s] = Pb[base + i0]; B1[s] = Pb[base + i1];
        V0[s] = Pv0[base + i0]; V1[s] = Pv0[base + i1];
        Qr[s] = Qs[p*4 + h];
    }
    #pragma unroll 1
    for (int p0 = NP - 1; p0 >= PF - 1; p0 -= PF) {
        #pragma unroll
        for (int s = 0; s < PF; s++) {
            int p = p0 - s;
            float4 cA0 = A0[s], cA1 = A1[s], cB0 = B0[s], cB1 = B1[s];
            float cV0 = V0[s], cV1 = V1[s];
            float2 cQ = Qr[s];
            // issue prefetch for pair p-PF into slot s
            int pn = p - PF;
            if (pn >= 0) {
                size_t nb = (size_t)pn*H;
                A0[s] = Pa[nb + i0]; A1[s] = Pa[nb + i1];
                B0[s] = Pb[nb + i0]; B1[s] = Pb[nb + i1];
                V0[s] = Pv0[nb + i0]; V1[s] = Pv0[nb + i1];
                Qr[s] = Qs[pn*4 + h];
            }
            // four independent reductions, interleaved butterflies
            float r1 = fmaf(u0, cA0.x, u1*cA1.x);   // c1 = u·kf1
            float r2 = fmaf(u0, cA0.y, u1*cA1.y);   // s1 = u·bv1
            float r3 = fmaf(u0, cA0.z, u1*cA1.z);   // m1 = u·(ew1∘kf0)
            float r4 = fmaf(u0, cA0.w, u1*cA1.w);   // m2 = u·(ew1∘bv0)
            #pragma unroll
            for (int off = 16; off; off >>= 1) {
                r1 += __shfl_xor_sync(0xffffffffu, r1, off);
                r2 += __shfl_xor_sync(0xffffffffu, r2, off);
                r3 += __shfl_xor_sync(0xffffffffu, r3, off);
                r4 += __shfl_xor_sync(0xffffffffu, r4, off);
            }
            float c0 = fmaf(-r2, cQ.x, r3);
            float s0 = fmaf(-r2, cQ.y, r4);
            o0 = fmaf(r1, cB0.w, fmaf(c0, cV0, o0));
            o1 = fmaf(r1, cB1.w, fmaf(c0, cV1, o1));
            u0 = fmaf(u0, cB0.x, -fmaf(r2, cB0.y, s0*cB0.z));
            u1 = fmaf(u1, cB1.x, -fmaf(r2, cB1.y, s0*cB1.z));
        }
    }
    // groupnorm over the head's 64 values
    float ms = wsum(o0 + o1);
    float sqs = wsum(fmaf(o0, o0, o1*o1));
    float mean = ms * (1.f/64.f);
    float var  = sqs * (1.f/64.f) - mean*mean;
    float inv  = rsqrtf(var + EPSc);
    float on0 = fmaf((o0 - mean)*inv, gn_w[i0], gn_b[i0]);
    float on1 = fmaf((o1 - mean)*inv, gn_w[i1], gn_b[i1]);
    // residual at t = T-1 (pair NP-1: kf1 = Pa.x, vv1 = Pb.w)
    size_t lb = (size_t)(NP-1)*H;
    float4 La0 = Pa[lb + i0], La1 = Pa[lb + i1];
    float4 Lb0 = Pb[lb + i0], Lb1 = Pb[lb + i1];
    float r0 = g_rlast[eb*H + i0], r1l = g_rlast[eb*H + i1];
    float rr = wsum(r0*La0.x*r_k[i0] + r1l*La1.x*r_k[i1]);
    on0 = fmaf(rr, Lb0.w, on0);
    on1 = fmaf(rr, Lb1.w, on1);
    g_o[eb*H + i0] = on0 * g_glast[eb*H + i0];
    g_o[eb*H + i1] = on1 * g_glast[eb*H + i1];
}

// ---------------- kF: out = g_o @ Wo^T ----------------
__global__ void k_out(const float* __restrict__ Wo, float* __restrict__ out) {
    int eb = blockIdx.x; int j = threadIdx.x;
    int w = j >> 5, ln = j & 31;
    __shared__ float os[H];
    os[j] = g_o[eb*H + j];
    __syncthreads();
    float xp[8];
    #pragma unroll
    for (int m = 0; m < 8; m++) xp[m] = os[ln*8 + m];
    #pragma unroll 1
    for (int rr = 0; rr < 32; rr++) {
        int n = rr*8 + w;
        const float4* Wrow = (const float4*)(Wo + n*H + ln*8);
        float4 a4 = Wrow[0], b4 = Wrow[1];
        float acc = xp[0]*a4.x + xp[1]*a4.y + xp[2]*a4.z + xp[3]*a4.w
                  + xp[4]*b4.x + xp[5]*b4.y + xp[6]*b4.z + xp[7]*b4.w;
        acc = wsum(acc);
        if (ln == 0) out[eb*H + n] = acc;
    }
}

// ---------------- launch ----------------
extern "C" void kernel_launch(void* const* d_in, const int* in_sizes, int n_in,
                              void* d_out, int out_size) {
    const float* query   = (const float*)d_in[0];
    const float* keyval  = (const float*)d_in[1];
    const float* v_first = (const float*)d_in[2];
    const float* x_r = (const float*)d_in[3];
    const float* x_w = (const float*)d_in[4];
    const float* x_k = (const float*)d_in[5];
    const float* x_v = (const float*)d_in[6];
    const float* x_a = (const float*)d_in[7];
    const float* x_g = (const float*)d_in[8];
    const float* w0  = (const float*)d_in[9];
    const float* w1  = (const float*)d_in[10];
    const float* w2  = (const float*)d_in[11];
    const float* a0  = (const float*)d_in[12];
    const float* a1  = (const float*)d_in[13];
    const float* a2  = (const float*)d_in[14];
    const float* v0  = (const float*)d_in[15];
    const float* v1  = (const float*)d_in[16];
    const float* v2  = (const float*)d_in[17];
    const float* g1  = (const float*)d_in[18];
    const float* g2  = (const float*)d_in[19];
    const float* k_k = (const float*)d_in[20];
    const float* k_a = (const float*)d_in[21];
    const float* r_k = (const float*)d_in[22];
    const float* Wr  = (const float*)d_in[23];
    const float* Wk  = (const float*)d_in[24];
    const float* Wv  = (const float*)d_in[25];
    const float* Wo  = (const float*)d_in[26];
    const float* gn_w = (const float*)d_in[27];
    const float* gn_b = (const float*)d_in[28];
    float* out = (float*)d_out;

    k_gemm_kv<<<dim3(BT/64, H/64, 2), 256>>>(keyval, x_k, x_v, Wk, Wv);
    k_bt<<<BT, H>>>(keyval, x_v, x_w, x_a, w1, v1, a1, v2, a2, v0, k_k);
    k_q<<<EB, H>>>(query, keyval, x_r, x_g, x_w, x_a, w1, a1, g1, a2, g2, Wr);
    k_pair<<<dim3(NP, EB), H>>>(v_first, w2, w0, a0, k_a);
    k_scan<<<EB*4, 32>>>(r_k, gn_w, gn_b);
    k_out<<<EB, H>>>(Wo, out);
    (void)in_sizes; (void)n_in; (void)out_size;
}